// round 1
// baseline (speedup 1.0000x reference)
#include <cuda_runtime.h>
#include <math.h>

#define NN 100000
#define FIN 128
#define FHID 32
#define FOUT 16
#define EPSV 1e-5f
#define NSLOPE 0.2f

// ---------------- scratch (device globals; allocation-free) ----------------
__device__ float g_bufA[NN * 64];   // ping
__device__ float g_bufB[NN * 64];   // pong
__device__ float g_dinv[NN];        // deg -> rsqrt(deg)
__device__ float g_als[NN * 2];
__device__ float g_ald[NN * 2];
__device__ float g_m[NN * 2];
__device__ float g_s[NN * 2];
__device__ unsigned g_menc[NN * 2];

// ---------------- helpers ----------------
__device__ __forceinline__ float lrelu(float x) {
    return x > 0.f ? x : NSLOPE * x;
}
// order-preserving float->uint encoding for atomicMax
__device__ __forceinline__ unsigned enc_f(float f) {
    unsigned u = __float_as_uint(f);
    return (u & 0x80000000u) ? ~u : (u | 0x80000000u);
}
__device__ __forceinline__ float dec_f(unsigned u) {
    return (u & 0x80000000u) ? __uint_as_float(u ^ 0x80000000u)
                             : __uint_as_float(~u);
}

// ---------------- degree / norm ----------------
__global__ void k_deg_init(int n) {
    int i = blockIdx.x * blockDim.x + threadIdx.x;
    if (i < n) g_dinv[i] = 1.0f;  // self loop
}
__global__ void k_deg_edge(const int* __restrict__ dst, int e) {
    int i = blockIdx.x * blockDim.x + threadIdx.x;
    if (i < e) atomicAdd(&g_dinv[dst[i]], 1.0f);
}
__global__ void k_deg_fin(int n) {
    int i = blockIdx.x * blockDim.x + threadIdx.x;
    if (i < n) g_dinv[i] = rsqrtf(g_dinv[i]);
}

// ---------------- small dense GEMM: Y[n,F] = X[n,K] @ W[K,F] ----------------
template <int K, int F>
__global__ void k_gemm(const float* __restrict__ X, const float* __restrict__ W,
                       float* __restrict__ Y, int n) {
    __shared__ float Ws[K * F];
    for (int i = threadIdx.x; i < K * F; i += blockDim.x) Ws[i] = W[i];
    __syncthreads();
    long idx = (long)blockIdx.x * blockDim.x + threadIdx.x;
    int row = (int)(idx / F);
    int col = (int)(idx % F);
    if (row >= n) return;
    const float* xr = X + (long)row * K;
    float acc = 0.f;
#pragma unroll
    for (int k = 0; k < K; ++k) acc = fmaf(__ldg(xr + k), Ws[k * F + col], acc);
    Y[(long)row * F + col] = acc;
}

// ---------------- GCN ----------------
// self-loop contribution also initializes the accumulator
template <int F>
__global__ void k_gcn_self(const float* __restrict__ h, float* __restrict__ acc, int n) {
    long idx = (long)blockIdx.x * blockDim.x + threadIdx.x;
    if (idx >= (long)n * F) return;
    int i = (int)(idx / F);
    float d = g_dinv[i];
    acc[idx] = h[idx] * d * d;
}
template <int F>
__global__ void k_gcn_edge(const float* __restrict__ h, float* __restrict__ acc,
                           const int* __restrict__ src, const int* __restrict__ dst, int e) {
    long gid = (long)blockIdx.x * blockDim.x + threadIdx.x;
    long ed = gid / F;
    int f = (int)(gid % F);
    if (ed >= e) return;
    int s = src[ed], d = dst[ed];
    float nrm = g_dinv[s] * g_dinv[d];
    atomicAdd(&acc[(long)d * F + f], __ldg(&h[(long)s * F + f]) * nrm);
}

// bias + BN(eval) + ReLU
__global__ void k_post_bn(const float* __restrict__ in, float* __restrict__ out,
                          const float* __restrict__ bias,
                          const float* __restrict__ bg, const float* __restrict__ bb,
                          const float* __restrict__ bm, const float* __restrict__ bv, int n) {
    long idx = (long)blockIdx.x * blockDim.x + threadIdx.x;
    if (idx >= (long)n * FHID) return;
    int c = (int)(idx % FHID);
    float v = in[idx] + __ldg(&bias[c]);
    float sc = __ldg(&bg[c]) * rsqrtf(__ldg(&bv[c]) + EPSV);
    float o = (v - __ldg(&bm[c])) * sc + __ldg(&bb[c]);
    out[idx] = fmaxf(o, 0.f);
}

// ---------------- GAT ----------------
// per-node attention logits: als[i,h] = <hg[i,h,:], a_src[h,:]>, ald likewise
template <int F>
__global__ void k_al(const float* __restrict__ hg, const float* __restrict__ a_s,
                     const float* __restrict__ a_d, int n) {
    int idx = blockIdx.x * blockDim.x + threadIdx.x;
    if (idx >= n * 2) return;
    int i = idx >> 1, h = idx & 1;
    const float* row = hg + (long)i * 2 * F + h * F;
    float s = 0.f, d = 0.f;
#pragma unroll
    for (int f = 0; f < F; ++f) {
        float v = __ldg(&row[f]);
        s = fmaf(v, __ldg(&a_s[h * F + f]), s);
        d = fmaf(v, __ldg(&a_d[h * F + f]), d);
    }
    g_als[idx] = s;
    g_ald[idx] = d;
}
__global__ void k_gat_selfmax(int n) {
    int idx = blockIdx.x * blockDim.x + threadIdx.x;
    if (idx >= n * 2) return;
    g_menc[idx] = enc_f(lrelu(g_als[idx] + g_ald[idx]));
}
__global__ void k_gat_edgemax(const int* __restrict__ src, const int* __restrict__ dst, int e) {
    int i = blockIdx.x * blockDim.x + threadIdx.x;
    if (i >= e) return;
    int s = src[i], d = dst[i];
#pragma unroll
    for (int h = 0; h < 2; ++h) {
        float ev = lrelu(g_als[s * 2 + h] + g_ald[d * 2 + h]);
        atomicMax(&g_menc[d * 2 + h], enc_f(ev));
    }
}
__global__ void k_gat_finmax(int n) {
    int idx = blockIdx.x * blockDim.x + threadIdx.x;
    if (idx >= n * 2) return;
    float m = dec_f(g_menc[idx]);
    g_m[idx] = m;
    g_s[idx] = expf(lrelu(g_als[idx] + g_ald[idx]) - m);  // self-loop term
}
__global__ void k_gat_edgesum(const int* __restrict__ src, const int* __restrict__ dst, int e) {
    int i = blockIdx.x * blockDim.x + threadIdx.x;
    if (i >= e) return;
    int s = src[i], d = dst[i];
#pragma unroll
    for (int h = 0; h < 2; ++h) {
        float ev = lrelu(g_als[s * 2 + h] + g_ald[d * 2 + h]);
        atomicAdd(&g_s[d * 2 + h], expf(ev - g_m[d * 2 + h]));
    }
}
// self-loop weighted contribution initializes accumulator; mean over 2 heads folded in
template <int F>
__global__ void k_gat_selfagg(const float* __restrict__ hg, float* __restrict__ acc, int n) {
    long idx = (long)blockIdx.x * blockDim.x + threadIdx.x;
    if (idx >= (long)n * F) return;
    int i = (int)(idx / F);
    int f = (int)(idx % F);
    float a0 = expf(lrelu(g_als[i * 2 + 0] + g_ald[i * 2 + 0]) - g_m[i * 2 + 0]) / g_s[i * 2 + 0];
    float a1 = expf(lrelu(g_als[i * 2 + 1] + g_ald[i * 2 + 1]) - g_m[i * 2 + 1]) / g_s[i * 2 + 1];
    const float* row = hg + (long)i * 2 * F;
    acc[idx] = 0.5f * (a0 * row[f] + a1 * row[F + f]);
}
template <int F>
__global__ void k_gat_edgeagg(const float* __restrict__ hg, float* __restrict__ acc,
                              const int* __restrict__ src, const int* __restrict__ dst, int e) {
    long gid = (long)blockIdx.x * blockDim.x + threadIdx.x;
    long ed = gid / F;
    int f = (int)(gid % F);
    if (ed >= e) return;
    int s = src[ed], d = dst[ed];
    float a0 = expf(lrelu(g_als[s * 2 + 0] + g_ald[d * 2 + 0]) - g_m[d * 2 + 0]) / g_s[d * 2 + 0];
    float a1 = expf(lrelu(g_als[s * 2 + 1] + g_ald[d * 2 + 1]) - g_m[d * 2 + 1]) / g_s[d * 2 + 1];
    const float* row = hg + (long)s * 2 * F;
    atomicAdd(&acc[(long)d * F + f], 0.5f * (a0 * __ldg(&row[f]) + a1 * __ldg(&row[F + f])));
}
// in-place bias + ReLU (after GAT1)
template <int F>
__global__ void k_bias_relu(float* __restrict__ buf, const float* __restrict__ b, int n) {
    long idx = (long)blockIdx.x * blockDim.x + threadIdx.x;
    if (idx >= (long)n * F) return;
    buf[idx] = fmaxf(buf[idx] + __ldg(&b[idx % F]), 0.f);
}

// ---------------- final: bias + log_softmax over 16 ----------------
__global__ void k_final(const float* __restrict__ acc, const float* __restrict__ b,
                        float* __restrict__ out, int n) {
    int i = blockIdx.x * blockDim.x + threadIdx.x;
    if (i >= n) return;
    float v[FOUT];
    float mx = -1e30f;
#pragma unroll
    for (int c = 0; c < FOUT; ++c) {
        v[c] = acc[(long)i * FOUT + c] + __ldg(&b[c]);
        mx = fmaxf(mx, v[c]);
    }
    float se = 0.f;
#pragma unroll
    for (int c = 0; c < FOUT; ++c) se += expf(v[c] - mx);
    float ls = logf(se) + mx;
#pragma unroll
    for (int c = 0; c < FOUT; ++c) out[(long)i * FOUT + c] = v[c] - ls;
}

// ---------------- host ----------------
static inline int cdiv(long a, int b) { return (int)((a + b - 1) / b); }

extern "C" void kernel_launch(void* const* d_in, const int* in_sizes, int n_in,
                              void* d_out, int out_size) {
    const float* x   = (const float*)d_in[0];
    const int*   ei  = (const int*)d_in[1];
    const float* g1W = (const float*)d_in[2];
    const float* g1b = (const float*)d_in[3];
    const float* b1g = (const float*)d_in[4];
    const float* b1b = (const float*)d_in[5];
    const float* b1m = (const float*)d_in[6];
    const float* b1v = (const float*)d_in[7];
    const float* a1W = (const float*)d_in[8];
    const float* a1s = (const float*)d_in[9];
    const float* a1d = (const float*)d_in[10];
    const float* a1b = (const float*)d_in[11];
    const float* g2W = (const float*)d_in[12];
    const float* g2b = (const float*)d_in[13];
    const float* b2g = (const float*)d_in[14];
    const float* b2b = (const float*)d_in[15];
    const float* b2m = (const float*)d_in[16];
    const float* b2v = (const float*)d_in[17];
    const float* a2W = (const float*)d_in[18];
    const float* a2s = (const float*)d_in[19];
    const float* a2d = (const float*)d_in[20];
    const float* a2b = (const float*)d_in[21];

    int n = in_sizes[0] / FIN;
    int e = in_sizes[1] / 2;
    const int* src = ei;
    const int* dst = ei + e;

    float *pA, *pB;
    cudaGetSymbolAddress((void**)&pA, g_bufA);
    cudaGetSymbolAddress((void**)&pB, g_bufB);

    const int B = 256;

    // degree / dinv
    k_deg_init<<<cdiv(n, B), B>>>(n);
    k_deg_edge<<<cdiv(e, B), B>>>(dst, e);
    k_deg_fin<<<cdiv(n, B), B>>>(n);

    // ---- GCN1: h1 = x @ W1; agg = D^-1/2 (A+I) D^-1/2 h1; h2 = relu(bn(agg + b)) ----
    k_gemm<FIN, FHID><<<cdiv((long)n * FHID, B), B>>>(x, g1W, pA, n);
    k_gcn_self<FHID><<<cdiv((long)n * FHID, B), B>>>(pA, pB, n);
    k_gcn_edge<FHID><<<cdiv((long)e * FHID, B), B>>>(pA, pB, src, dst, e);
    k_post_bn<<<cdiv((long)n * FHID, B), B>>>(pB, pA, g1b, b1g, b1b, b1m, b1v, n);

    // ---- GAT1 (HID->HID, 2 heads, mean) ----
    k_gemm<FHID, 2 * FHID><<<cdiv((long)n * 2 * FHID, B), B>>>(pA, a1W, pB, n);
    k_al<FHID><<<cdiv(n * 2, B), B>>>(pB, a1s, a1d, n);
    k_gat_selfmax<<<cdiv(n * 2, B), B>>>(n);
    k_gat_edgemax<<<cdiv(e, B), B>>>(src, dst, e);
    k_gat_finmax<<<cdiv(n * 2, B), B>>>(n);
    k_gat_edgesum<<<cdiv(e, B), B>>>(src, dst, e);
    k_gat_selfagg<FHID><<<cdiv((long)n * FHID, B), B>>>(pB, pA, n);
    k_gat_edgeagg<FHID><<<cdiv((long)e * FHID, B), B>>>(pB, pA, src, dst, e);
    k_bias_relu<FHID><<<cdiv((long)n * FHID, B), B>>>(pA, a1b, n);

    // ---- GCN2 ----
    k_gemm<FHID, FHID><<<cdiv((long)n * FHID, B), B>>>(pA, g2W, pB, n);
    k_gcn_self<FHID><<<cdiv((long)n * FHID, B), B>>>(pB, pA, n);
    k_gcn_edge<FHID><<<cdiv((long)e * FHID, B), B>>>(pB, pA, src, dst, e);
    k_post_bn<<<cdiv((long)n * FHID, B), B>>>(pA, pA, g2b, b2g, b2b, b2m, b2v, n);

    // ---- GAT2 (HID->OUT, 2 heads, mean) ----
    k_gemm<FHID, 2 * FOUT><<<cdiv((long)n * 2 * FOUT, B), B>>>(pA, a2W, pB, n);
    k_al<FOUT><<<cdiv(n * 2, B), B>>>(pB, a2s, a2d, n);
    k_gat_selfmax<<<cdiv(n * 2, B), B>>>(n);
    k_gat_edgemax<<<cdiv(e, B), B>>>(src, dst, e);
    k_gat_finmax<<<cdiv(n * 2, B), B>>>(n);
    k_gat_edgesum<<<cdiv(e, B), B>>>(src, dst, e);
    k_gat_selfagg<FOUT><<<cdiv((long)n * FOUT, B), B>>>(pB, pA, n);
    k_gat_edgeagg<FOUT><<<cdiv((long)e * FOUT, B), B>>>(pB, pA, src, dst, e);

    // ---- final log_softmax ----
    k_final<<<cdiv(n, B), B>>>(pA, a2b, (float*)d_out, n);
}

// round 2
// speedup vs baseline: 1.7109x; 1.7109x over previous
#include <cuda_runtime.h>
#include <math.h>

#define NN 100000
#define EMAX 1600000
#define FIN 128
#define FHID 32
#define FOUT 16
#define EPSV 1e-5f
#define NSLOPE 0.2f

// ---------------- scratch (device globals; allocation-free) ----------------
__device__ float g_bufA[NN * 64];
__device__ float g_bufB[NN * 64];
__device__ float g_dinv[NN];
__device__ int   g_deg[NN];
__device__ int   g_rowptr[NN + 1];
__device__ int   g_cursor[NN];
__device__ int   g_csr[EMAX];
__device__ float g_als[NN * 2];
__device__ float g_ald[NN * 2];

// ---------------- helpers ----------------
__device__ __forceinline__ float lrelu(float x) { return x > 0.f ? x : NSLOPE * x; }
__device__ __forceinline__ float wmax32(float v) {
#pragma unroll
    for (int o = 16; o; o >>= 1) v = fmaxf(v, __shfl_xor_sync(0xffffffffu, v, o));
    return v;
}
__device__ __forceinline__ float wsum32(float v) {
#pragma unroll
    for (int o = 16; o; o >>= 1) v += __shfl_xor_sync(0xffffffffu, v, o);
    return v;
}

// ---------------- CSR build ----------------
__global__ void k_zero_deg(int n) {
    int i = blockIdx.x * blockDim.x + threadIdx.x;
    if (i < n) g_deg[i] = 0;
}
__global__ void k_hist(const int* __restrict__ dst, int e) {
    int i = blockIdx.x * blockDim.x + threadIdx.x;
    if (i < e) atomicAdd(&g_deg[dst[i]], 1);
}
// single-block chunked exclusive scan; also writes cursor and dinv
__global__ void k_scan(int n) {
    __shared__ int ssum[1024];
    int t = threadIdx.x;
    int chunk = (n + 1023) / 1024;
    int lo = t * chunk, hi = min(lo + chunk, n);
    int s = 0;
    for (int i = lo; i < hi; ++i) s += g_deg[i];
    ssum[t] = s;
    __syncthreads();
#pragma unroll
    for (int off = 1; off < 1024; off <<= 1) {
        int v = (t >= off) ? ssum[t - off] : 0;
        __syncthreads();
        ssum[t] += v;
        __syncthreads();
    }
    int run = t ? ssum[t - 1] : 0;
    for (int i = lo; i < hi; ++i) {
        int d = g_deg[i];
        g_rowptr[i] = run;
        g_cursor[i] = run;
        g_dinv[i] = rsqrtf((float)(d + 1));
        run += d;
    }
    if (t == 1023) g_rowptr[n] = ssum[1023];
}
__global__ void k_scatter(const int* __restrict__ src, const int* __restrict__ dst, int e) {
    int i = blockIdx.x * blockDim.x + threadIdx.x;
    if (i >= e) return;
    int pos = atomicAdd(&g_cursor[dst[i]], 1);
    g_csr[pos] = src[i];
}

// ---------------- tiled GEMM: Y[n,F] = X[n,K] @ W[K,F] ----------------
template <int K, int F, int RPB>
__global__ void k_gemm_t(const float* __restrict__ X, const float* __restrict__ W,
                         float* __restrict__ Y, int n) {
    constexpr int RPT = RPB * F / 256;
    __shared__ float Ws[K * F];
    __shared__ float Xs[RPB * K];
    int tid = threadIdx.x;
    for (int i = tid; i < K * F; i += 256) Ws[i] = W[i];
    int row0 = blockIdx.x * RPB;
    for (int i = tid; i < RPB * K; i += 256) {
        int r = row0 + i / K;
        Xs[i] = (r < n) ? X[(long)r * K + (i % K)] : 0.f;
    }
    __syncthreads();
    int col = tid % F, rg = tid / F;
    float acc[RPT];
#pragma unroll
    for (int r = 0; r < RPT; ++r) acc[r] = 0.f;
#pragma unroll 8
    for (int k = 0; k < K; ++k) {
        float wv = Ws[k * F + col];
#pragma unroll
        for (int r = 0; r < RPT; ++r)
            acc[r] = fmaf(Xs[(rg * RPT + r) * K + k], wv, acc[r]);
    }
#pragma unroll
    for (int r = 0; r < RPT; ++r) {
        int row = row0 + rg * RPT + r;
        if (row < n) Y[(long)row * F + col] = acc[r];
    }
}

// ---------------- GCN gather (warp/node) + bias + BN + ReLU ----------------
__global__ void k_gcn_agg(const float* __restrict__ h, float* __restrict__ out,
                          const float* __restrict__ bias,
                          const float* __restrict__ bg, const float* __restrict__ bb,
                          const float* __restrict__ bm, const float* __restrict__ bv, int n) {
    int w = (blockIdx.x * blockDim.x + threadIdx.x) >> 5;
    int lane = threadIdx.x & 31;
    if (w >= n) return;
    int r0 = g_rowptr[w], r1 = g_rowptr[w + 1];
    float dd = g_dinv[w];
    float acc = h[(long)w * FHID + lane] * dd;   // self contribution (norm = dd*dd)
    for (int j = r0; j < r1; ++j) {
        int s = g_csr[j];
        acc = fmaf(h[(long)s * FHID + lane], g_dinv[s], acc);
    }
    acc = acc * dd + __ldg(&bias[lane]);
    float sc = __ldg(&bg[lane]) * rsqrtf(__ldg(&bv[lane]) + EPSV);
    float o = (acc - __ldg(&bm[lane])) * sc + __ldg(&bb[lane]);
    out[(long)w * FHID + lane] = fmaxf(o, 0.f);
}

// ---------------- per-node attention logits (warp/node) ----------------
template <int F>
__global__ void k_al(const float* __restrict__ hg, const float* __restrict__ a_s,
                     const float* __restrict__ a_d, int n) {
    int w = (blockIdx.x * blockDim.x + threadIdx.x) >> 5;
    int lane = threadIdx.x & 31;
    if (w >= n) return;
    if (F == 32) {
        float v0 = hg[(long)w * 64 + lane];
        float v1 = hg[(long)w * 64 + 32 + lane];
        float s0 = wsum32(v0 * __ldg(&a_s[lane]));
        float d0 = wsum32(v0 * __ldg(&a_d[lane]));
        float s1 = wsum32(v1 * __ldg(&a_s[32 + lane]));
        float d1 = wsum32(v1 * __ldg(&a_d[32 + lane]));
        if (lane == 0) {
            g_als[w * 2] = s0; g_als[w * 2 + 1] = s1;
            g_ald[w * 2] = d0; g_ald[w * 2 + 1] = d1;
        }
    } else {  // F == 16: lane = head*16 + f; a_s laid out [2,16] = 32 floats
        float v = hg[(long)w * 32 + lane];
        float s = v * __ldg(&a_s[lane]);
        float d = v * __ldg(&a_d[lane]);
#pragma unroll
        for (int o = 8; o; o >>= 1) {
            s += __shfl_xor_sync(0xffffffffu, s, o);
            d += __shfl_xor_sync(0xffffffffu, d, o);
        }
        if ((lane & 15) == 0) {
            g_als[w * 2 + (lane >> 4)] = s;
            g_ald[w * 2 + (lane >> 4)] = d;
        }
    }
}

// ---------------- fused GAT (warp/node): softmax + aggregate + epilogue ----------------
// MODE 0: F=32, epilogue = bias + ReLU
// MODE 1: F=16, epilogue = bias + log_softmax (final output)
template <int F, int MODE>
__global__ void k_gat_agg(const float* __restrict__ hg, float* __restrict__ out,
                          const float* __restrict__ bias, int n) {
    int w = (blockIdx.x * blockDim.x + threadIdx.x) >> 5;
    int lane = threadIdx.x & 31;
    if (w >= n) return;
    int r0 = g_rowptr[w], r1 = g_rowptr[w + 1];
    float ald0 = g_ald[w * 2], ald1 = g_ald[w * 2 + 1];
    float es0 = lrelu(g_als[w * 2] + ald0);
    float es1 = lrelu(g_als[w * 2 + 1] + ald1);
    // pass 1: max
    float m0 = es0, m1 = es1;
    for (int j = r0 + lane; j < r1; j += 32) {
        int s = g_csr[j];
        m0 = fmaxf(m0, lrelu(g_als[s * 2] + ald0));
        m1 = fmaxf(m1, lrelu(g_als[s * 2 + 1] + ald1));
    }
    m0 = wmax32(m0); m1 = wmax32(m1);
    // pass 2: sum
    float s0 = (lane == 0) ? expf(es0 - m0) : 0.f;
    float s1 = (lane == 0) ? expf(es1 - m1) : 0.f;
    for (int j = r0 + lane; j < r1; j += 32) {
        int s = g_csr[j];
        s0 += expf(lrelu(g_als[s * 2] + ald0) - m0);
        s1 += expf(lrelu(g_als[s * 2 + 1] + ald1) - m1);
    }
    s0 = wsum32(s0); s1 = wsum32(s1);

    if (MODE == 0) {  // F = 32
        float acc0 = expf(es0 - m0) * hg[(long)w * 64 + lane];
        float acc1 = expf(es1 - m1) * hg[(long)w * 64 + 32 + lane];
        for (int base = r0; base < r1; base += 32) {
            int j = base + lane;
            int cnt = min(32, r1 - base);
            int sj = 0; float a0 = 0.f, a1 = 0.f;
            if (j < r1) {
                sj = g_csr[j];
                a0 = expf(lrelu(g_als[sj * 2] + ald0) - m0);
                a1 = expf(lrelu(g_als[sj * 2 + 1] + ald1) - m1);
            }
            for (int q = 0; q < cnt; ++q) {
                int s = __shfl_sync(0xffffffffu, sj, q);
                float b0 = __shfl_sync(0xffffffffu, a0, q);
                float b1 = __shfl_sync(0xffffffffu, a1, q);
                acc0 = fmaf(b0, hg[(long)s * 64 + lane], acc0);
                acc1 = fmaf(b1, hg[(long)s * 64 + 32 + lane], acc1);
            }
        }
        float o = acc0 * (0.5f / s0) + acc1 * (0.5f / s1) + __ldg(&bias[lane]);
        out[(long)w * 32 + lane] = fmaxf(o, 0.f);
    } else {  // F = 16, lane = head*16 + f
        int head = lane >> 4;
        float m_h = head ? m1 : m0;
        float s_h = head ? s1 : s0;
        float es_h = head ? es1 : es0;
        float acc = expf(es_h - m_h) * hg[(long)w * 32 + lane];
        for (int base = r0; base < r1; base += 32) {
            int j = base + lane;
            int cnt = min(32, r1 - base);
            int sj = 0; float a0 = 0.f, a1 = 0.f;
            if (j < r1) {
                sj = g_csr[j];
                a0 = expf(lrelu(g_als[sj * 2] + ald0) - m0);
                a1 = expf(lrelu(g_als[sj * 2 + 1] + ald1) - m1);
            }
            for (int q = 0; q < cnt; ++q) {
                int s = __shfl_sync(0xffffffffu, sj, q);
                float b0 = __shfl_sync(0xffffffffu, a0, q);
                float b1 = __shfl_sync(0xffffffffu, a1, q);
                acc = fmaf(head ? b1 : b0, hg[(long)s * 32 + lane], acc);
            }
        }
        float v = acc / s_h;
        v = 0.5f * (v + __shfl_xor_sync(0xffffffffu, v, 16));  // mean over heads
        v += __ldg(&bias[lane & 15]);
        // log_softmax over 16 classes (duplicated across halves)
        float mx = v;
#pragma unroll
        for (int o = 8; o; o >>= 1) mx = fmaxf(mx, __shfl_xor_sync(0xffffffffu, mx, o));
        float se = expf(v - mx);
#pragma unroll
        for (int o = 8; o; o >>= 1) se += __shfl_xor_sync(0xffffffffu, se, o);
        float ls = logf(se) + mx;
        if (lane < 16) out[(long)w * 16 + lane] = v - ls;
    }
}

// ---------------- host ----------------
static inline int cdiv(long a, int b) { return (int)((a + b - 1) / b); }

extern "C" void kernel_launch(void* const* d_in, const int* in_sizes, int n_in,
                              void* d_out, int out_size) {
    const float* x   = (const float*)d_in[0];
    const int*   ei  = (const int*)d_in[1];
    const float* g1W = (const float*)d_in[2];
    const float* g1b = (const float*)d_in[3];
    const float* b1g = (const float*)d_in[4];
    const float* b1b = (const float*)d_in[5];
    const float* b1m = (const float*)d_in[6];
    const float* b1v = (const float*)d_in[7];
    const float* a1W = (const float*)d_in[8];
    const float* a1s = (const float*)d_in[9];
    const float* a1d = (const float*)d_in[10];
    const float* a1b = (const float*)d_in[11];
    const float* g2W = (const float*)d_in[12];
    const float* g2b = (const float*)d_in[13];
    const float* b2g = (const float*)d_in[14];
    const float* b2b = (const float*)d_in[15];
    const float* b2m = (const float*)d_in[16];
    const float* b2v = (const float*)d_in[17];
    const float* a2W = (const float*)d_in[18];
    const float* a2s = (const float*)d_in[19];
    const float* a2d = (const float*)d_in[20];
    const float* a2b = (const float*)d_in[21];

    int n = in_sizes[0] / FIN;
    int e = in_sizes[1] / 2;
    const int* src = ei;
    const int* dst = ei + e;

    float *pA, *pB;
    cudaGetSymbolAddress((void**)&pA, g_bufA);
    cudaGetSymbolAddress((void**)&pB, g_bufB);

    const int B = 256;
    int nwarp_blocks = cdiv((long)n * 32, B);  // warp-per-node grids

    // ---- CSR build ----
    k_zero_deg<<<cdiv(n, B), B>>>(n);
    k_hist<<<cdiv(e, B), B>>>(dst, e);
    k_scan<<<1, 1024>>>(n);
    k_scatter<<<cdiv(e, B), B>>>(src, dst, e);

    // ---- GCN1 ----
    k_gemm_t<FIN, FHID, 32><<<cdiv(n, 32), B>>>(x, g1W, pA, n);
    k_gcn_agg<<<nwarp_blocks, B>>>(pA, pB, g1b, b1g, b1b, b1m, b1v, n);

    // ---- GAT1 (HID->HID, 2 heads, mean) ----
    k_gemm_t<FHID, 64, 16><<<cdiv(n, 16), B>>>(pB, a1W, pA, n);
    k_al<32><<<nwarp_blocks, B>>>(pA, a1s, a1d, n);
    k_gat_agg<32, 0><<<nwarp_blocks, B>>>(pA, pB, a1b, n);

    // ---- GCN2 ----
    k_gemm_t<FHID, FHID, 32><<<cdiv(n, 32), B>>>(pB, g2W, pA, n);
    k_gcn_agg<<<nwarp_blocks, B>>>(pA, pB, g2b, b2g, b2b, b2m, b2v, n);

    // ---- GAT2 (HID->OUT, 2 heads, mean) + final log_softmax ----
    k_gemm_t<FHID, 2 * FOUT, 32><<<cdiv(n, 32), B>>>(pB, a2W, pA, n);
    k_al<16><<<nwarp_blocks, B>>>(pA, a2s, a2d, n);
    k_gat_agg<16, 1><<<nwarp_blocks, B>>>(pA, (float*)d_out, a2b, n);
}